// round 3
// baseline (speedup 1.0000x reference)
#include <cuda_runtime.h>
#include <cuda_bf16.h>

#define NMAX   100000
#define EMAX   1600000
#define CIN_   128
#define COUT_  64
#define SCAN_C 1024
#define NBLK_MAX 128

// Scratch (device globals — no allocation allowed)
__device__ float g_H[NMAX * COUT_];
__device__ float g_dinv[NMAX];
__device__ int   g_deg[NMAX];          // zero at entry of every call (restored by scan1)
__device__ int   g_rowoff[NMAX + 1];
__device__ int   g_pos[EMAX];
__device__ int2  g_edge[EMAX];         // {src, bitcast(dinv[src])}
__device__ int   g_bsum[NBLK_MAX];

// ---------------------------------------------------------------------------
// A) fused: per-block edge-slice degree atomics (records slot), then GEMM tile
//    GEMM: H = X @ W + b via packed fma.rn.f32x2 (2 lanes/issue)
// ---------------------------------------------------------------------------
#define FMA2(d, a, b) asm("fma.rn.f32x2 %0, %1, %2, %3;" \
                          : "=l"(d) : "l"(a), "l"(b), "l"(d))

__global__ __launch_bounds__(256) void gemm_deg_kernel(
    const float* __restrict__ X, const float* __restrict__ W,
    const float* __restrict__ bias,
    const int* __restrict__ dst, int n, int E)
{
    // ---- edge slice: deg atomics (overlaps with FMA work of other blocks) ----
    {
        int nb    = gridDim.x;
        int chunk = (E + nb - 1) / nb;
        int e0    = blockIdx.x * chunk;
        int e1    = min(e0 + chunk, E);
        for (int i = e0 + threadIdx.x; i < e1; i += 256) {
            int d = dst[i];
            g_pos[i] = atomicAdd(&g_deg[d], 1);
        }
    }

    // ---- GEMM tile: 128 rows x 64 cols ----
    __shared__ float2 Xs2[16][130];   // duplicated (x,x) pairs
    __shared__ float  Ws[16][64];

    const int tid  = threadIdx.x;
    const int tcol = tid & 15;        // cols tcol*4 .. +3
    const int trow = tid >> 4;        // rows trow*8 .. +7
    const int row0 = blockIdx.x * 128;

    if (row0 >= n) return;

    unsigned long long acc[8][2];
    #pragma unroll
    for (int r = 0; r < 8; r++) { acc[r][0] = 0ull; acc[r][1] = 0ull; }

    for (int k0 = 0; k0 < CIN_; k0 += 16) {
        #pragma unroll
        for (int p = 0; p < 2; p++) {
            int r  = p * 64 + (tid >> 2);
            int kq = tid & 3;
            int rr = row0 + r;
            const float* xp = X + (long)(rr < n ? rr : 0) * CIN_ + k0 + kq * 4;
            float4 v = *(const float4*)xp;
            Xs2[kq * 4 + 0][r] = make_float2(v.x, v.x);
            Xs2[kq * 4 + 1][r] = make_float2(v.y, v.y);
            Xs2[kq * 4 + 2][r] = make_float2(v.z, v.z);
            Xs2[kq * 4 + 3][r] = make_float2(v.w, v.w);
        }
        {
            int k    = tid >> 4;
            int colq = tid & 15;
            float4 v = *(const float4*)(W + (long)(k0 + k) * COUT_ + colq * 4);
            *(float4*)&Ws[k][colq * 4] = v;
        }
        __syncthreads();

        #pragma unroll
        for (int kk = 0; kk < 16; kk++) {
            ulonglong2 a01 = *(const ulonglong2*)&Xs2[kk][trow * 8 + 0];
            ulonglong2 a23 = *(const ulonglong2*)&Xs2[kk][trow * 8 + 2];
            ulonglong2 a45 = *(const ulonglong2*)&Xs2[kk][trow * 8 + 4];
            ulonglong2 a67 = *(const ulonglong2*)&Xs2[kk][trow * 8 + 6];
            ulonglong2 b   = *(const ulonglong2*)&Ws[kk][tcol * 4];
            FMA2(acc[0][0], a01.x, b.x);  FMA2(acc[0][1], a01.x, b.y);
            FMA2(acc[1][0], a01.y, b.x);  FMA2(acc[1][1], a01.y, b.y);
            FMA2(acc[2][0], a23.x, b.x);  FMA2(acc[2][1], a23.x, b.y);
            FMA2(acc[3][0], a23.y, b.x);  FMA2(acc[3][1], a23.y, b.y);
            FMA2(acc[4][0], a45.x, b.x);  FMA2(acc[4][1], a45.x, b.y);
            FMA2(acc[5][0], a45.y, b.x);  FMA2(acc[5][1], a45.y, b.y);
            FMA2(acc[6][0], a67.x, b.x);  FMA2(acc[6][1], a67.x, b.y);
            FMA2(acc[7][0], a67.y, b.x);  FMA2(acc[7][1], a67.y, b.y);
        }
        __syncthreads();
    }

    float4 bb = *(const float4*)(bias + tcol * 4);
    #pragma unroll
    for (int r = 0; r < 8; r++) {
        int row = row0 + trow * 8 + r;
        if (row < n) {
            float2 lo = *(const float2*)&acc[r][0];
            float2 hi = *(const float2*)&acc[r][1];
            float4 o;
            o.x = lo.x + bb.x;  o.y = lo.y + bb.y;
            o.z = hi.x + bb.z;  o.w = hi.y + bb.w;
            *(float4*)&g_H[(long)row * COUT_ + tcol * 4] = o;
        }
    }
}

// ---------------------------------------------------------------------------
// B) scan stage 1: per-block exclusive scan of deg (1024/block), computes
//    dinv = rsqrt(1+deg), and clears deg back to 0 (restores invariant)
// ---------------------------------------------------------------------------
__global__ __launch_bounds__(256) void scan1_kernel(int n) {
    __shared__ int wsum[8];
    const int b    = blockIdx.x;
    const int base = b * SCAN_C + threadIdx.x * 4;
    const int lane = threadIdx.x & 31;
    const int warp = threadIdx.x >> 5;

    int v[4];
    #pragma unroll
    for (int i = 0; i < 4; i++) {
        int idx = base + i;
        v[i] = (idx < n) ? g_deg[idx] : 0;
        if (idx < n) {
            g_dinv[idx] = rsqrtf(1.0f + (float)v[i]);
            g_deg[idx]  = 0;                    // restore for next call
        }
    }
    int tsum = v[0] + v[1] + v[2] + v[3];

    int x = tsum;
    #pragma unroll
    for (int off = 1; off < 32; off <<= 1) {
        int y = __shfl_up_sync(0xFFFFFFFFu, x, off);
        if (lane >= off) x += y;
    }
    if (lane == 31) wsum[warp] = x;
    __syncthreads();
    if (threadIdx.x == 0) {
        int run = 0;
        #pragma unroll
        for (int w = 0; w < 8; w++) { int t = wsum[w]; wsum[w] = run; run += t; }
        g_bsum[b] = run;
    }
    __syncthreads();

    int run = wsum[warp] + x - tsum;
    #pragma unroll
    for (int i = 0; i < 4; i++) {
        int idx = base + i;
        if (idx < n) g_rowoff[idx] = run;
        run += v[i];
    }
}

// ---------------------------------------------------------------------------
// C) fused scan2+scan3: every block scans bsum locally (<=128 entries) and
//    adds its offset to its 1024 rowoff entries; last block writes sentinel.
// ---------------------------------------------------------------------------
__global__ __launch_bounds__(256) void scan23_kernel(int n, int nblk, int E) {
    __shared__ int sp[NBLK_MAX];
    const int t = threadIdx.x;
    const int b = blockIdx.x;

    if (t < nblk) sp[t] = g_bsum[t];
    __syncthreads();
    // Hillis-Steele inclusive scan over nblk entries
    for (int s = 1; s < NBLK_MAX; s <<= 1) {
        int v = 0;
        if (t < nblk && t >= s) v = sp[t - s];
        __syncthreads();
        if (t < nblk) sp[t] += v;
        __syncthreads();
    }
    int off = (b == 0) ? 0 : sp[b - 1];

    const int base = b * SCAN_C + t * 4;
    if (base < n) {
        int4* p = (int4*)&g_rowoff[base];
        int4 r = *p;
        r.x += off;
        if (base + 1 < n) r.y += off;
        if (base + 2 < n) r.z += off;
        if (base + 3 < n) r.w += off;
        *p = r;
    }
    if (b == nblk - 1 && t == 0) g_rowoff[n] = E;
}

// ---------------------------------------------------------------------------
// D) CSR fill (no atomics): edge[rowoff[d] + pos[i]] = {src, dinv[src]}
// ---------------------------------------------------------------------------
__global__ __launch_bounds__(256) void fill_kernel(
    const int* __restrict__ src, const int* __restrict__ dst, int E)
{
    int i = blockIdx.x * blockDim.x + threadIdx.x;
    if (i >= E) return;
    int s = src[i];
    int d = dst[i];
    int p = g_pos[i];
    g_edge[g_rowoff[d] + p] = make_int2(s, __float_as_int(g_dinv[s]));
}

// ---------------------------------------------------------------------------
// E) gather: one warp per node, float2 per lane (covers 64 cols)
//    out[d] = relu( sum_e dinv[s]*dinv[d]*H[s] + H[d]*dinv[d]^2 )
// ---------------------------------------------------------------------------
__global__ __launch_bounds__(256) void gather_kernel(float* __restrict__ out, int n) {
    int node = (blockIdx.x * 256 + threadIdx.x) >> 5;
    if (node >= n) return;
    int lane = threadIdx.x & 31;

    float dd = g_dinv[node];
    int   r0 = g_rowoff[node];
    int   m  = g_rowoff[node + 1] - r0;

    long off = (long)node * COUT_ + lane * 2;
    float2 h = *(const float2*)&g_H[off];
    float self = dd * dd;
    float2 acc = make_float2(h.x * self, h.y * self);

    const int2* ep = &g_edge[r0];
    int j = 0;
    for (; j + 4 <= m; j += 4) {
        int2 e0 = ep[j], e1 = ep[j + 1], e2 = ep[j + 2], e3 = ep[j + 3];
        float2 h0 = *(const float2*)&g_H[(long)e0.x * COUT_ + lane * 2];
        float2 h1 = *(const float2*)&g_H[(long)e1.x * COUT_ + lane * 2];
        float2 h2 = *(const float2*)&g_H[(long)e2.x * COUT_ + lane * 2];
        float2 h3 = *(const float2*)&g_H[(long)e3.x * COUT_ + lane * 2];
        float c0 = __int_as_float(e0.y) * dd;
        float c1 = __int_as_float(e1.y) * dd;
        float c2 = __int_as_float(e2.y) * dd;
        float c3 = __int_as_float(e3.y) * dd;
        acc.x = fmaf(h0.x, c0, acc.x); acc.y = fmaf(h0.y, c0, acc.y);
        acc.x = fmaf(h1.x, c1, acc.x); acc.y = fmaf(h1.y, c1, acc.y);
        acc.x = fmaf(h2.x, c2, acc.x); acc.y = fmaf(h2.y, c2, acc.y);
        acc.x = fmaf(h3.x, c3, acc.x); acc.y = fmaf(h3.y, c3, acc.y);
    }
    for (; j < m; j++) {
        int2 e = ep[j];
        float co = __int_as_float(e.y) * dd;
        float2 hh = *(const float2*)&g_H[(long)e.x * COUT_ + lane * 2];
        acc.x = fmaf(hh.x, co, acc.x); acc.y = fmaf(hh.y, co, acc.y);
    }

    float2 o = make_float2(fmaxf(acc.x, 0.0f), fmaxf(acc.y, 0.0f));
    *(float2*)&out[off] = o;
}

// ---------------------------------------------------------------------------
extern "C" void kernel_launch(void* const* d_in, const int* in_sizes, int n_in,
                              void* d_out, int out_size)
{
    const float* X    = (const float*)d_in[0];   // (N, 128)
    const float* W    = (const float*)d_in[1];   // (128, 64)
    const float* bias = (const float*)d_in[2];   // (64,)
    const int*   src  = (const int*)d_in[3];     // (E,)
    const int*   dst  = (const int*)d_in[4];     // (E,)
    float*       out  = (float*)d_out;           // (N, 64)

    const int n = in_sizes[0] / CIN_;
    const int E = in_sizes[3];
    const int nblk = (n + SCAN_C - 1) / SCAN_C;

    // A) GEMM + degree atomics (fused; deg must be 0 on entry — invariant
    //    restored by scan1 each call, static zero-init on first call)
    gemm_deg_kernel<<<(n + 127) / 128, 256>>>(X, W, bias, dst, n, E);
    // B) per-chunk scan + dinv + deg clear
    scan1_kernel<<<nblk, 256>>>(n);
    // C) global offsets + sentinel
    scan23_kernel<<<nblk, 256>>>(n, nblk, E);
    // D) CSR fill (atomic-free)
    fill_kernel<<<(E + 255) / 256, 256>>>(src, dst, E);
    // E) gather + ReLU
    gather_kernel<<<(int)(((long)n * 32 + 255) / 256), 256>>>(out, n);
}